// round 1
// baseline (speedup 1.0000x reference)
#include <cuda_runtime.h>
#include <math.h>

#define Bc 4
#define Lc 256
#define Ec 128
#define Hc 8
#define Dh 16
#define NUc 512
#define NTc 256

// ---------------- scratch (device globals; no allocation) ----------------
__device__ float g_q_uu[Bc*Lc*Ec];
__device__ float g_q_ta[Bc*Lc*Ec];
__device__ float g_q_du[Bc*Lc*Ec];
__device__ float g_k_ta[Bc*NTc*Ec];
__device__ float g_v_ta[Bc*NTc*Ec];
__device__ float g_k_du[Bc*Lc*Ec];
__device__ float g_v_du[Bc*Lc*Ec];
__device__ float g_kb_uu[Bc*NUc*Ec];
__device__ float g_vb_uu[Bc*NUc*Ec];
__device__ float g_o_uu[Bc*Lc*Ec];
__device__ float g_o_ta[Bc*Lc*Ec];
__device__ float g_o_du[Bc*Lc*Ec];
__device__ float g_W1T[Ec*Ec];
__device__ float g_W2T[Ec*Ec];
__device__ float g_W3T[Ec*Ec];
__device__ float g_bcomb[Ec];
__device__ float g_y[Bc*Lc*Ec];
__device__ float g_mean[Ec];
__device__ float g_rstd[Ec];

// ---------------- combined output-projection weights ----------------
// y = o_uu @ W1^T + o_ta @ W2^T + o_du @ W3^T + bcomb
// W_m[e,j] = sum_k dim_w[e, m*128+k] * out_w_m[k, j]; stored transposed WmT[j*128+e]
__global__ void combine_w(const float* __restrict__ dim_w, const float* __restrict__ dim_b,
                          const float* __restrict__ uu_ow, const float* __restrict__ uu_ob,
                          const float* __restrict__ ta_ow, const float* __restrict__ ta_ob,
                          const float* __restrict__ du_ow, const float* __restrict__ du_ob)
{
    int tid = blockIdx.x * 256 + threadIdx.x;
    if (tid < 3 * Ec * Ec) {
        int m = tid / (Ec * Ec);
        int rem = tid % (Ec * Ec);
        int j = rem / Ec;
        int e = rem % Ec;
        const float* ow = (m == 0) ? uu_ow : (m == 1) ? ta_ow : du_ow;
        const float* dw = dim_w + (size_t)e * (3 * Ec) + m * Ec;
        float acc = 0.f;
        #pragma unroll 4
        for (int k = 0; k < Ec; k++) acc += dw[k] * ow[k * Ec + j];
        float* dst = (m == 0) ? g_W1T : (m == 1) ? g_W2T : g_W3T;
        dst[j * Ec + e] = acc;
    } else if (tid < 3 * Ec * Ec + Ec) {
        int e = tid - 3 * Ec * Ec;
        float acc = dim_b[e];
        const float* dw = dim_w + (size_t)e * (3 * Ec);
        for (int k = 0; k < Ec; k++) {
            acc += dw[k] * uu_ob[k] + dw[Ec + k] * ta_ob[k] + dw[2 * Ec + k] * du_ob[k];
        }
        g_bcomb[e] = acc;
    }
}

// ---------------- all input projections in one launch (blockIdx.z selects) ----------------
// out[M,128] = X[M,K] @ W^T + bias   (W rows stride 128)
__global__ void proj_all(const float* __restrict__ UU, const float* __restrict__ DU,
                         const float* __restrict__ TA,
                         const float* __restrict__ uu_iw, const float* __restrict__ uu_ib,
                         const float* __restrict__ ta_iw, const float* __restrict__ ta_ib,
                         const float* __restrict__ du_iw, const float* __restrict__ du_ib)
{
    const float *X, *W, *bias;
    float* out;
    int K = Ec, sx = Ec, M = Bc * Lc;
    switch (blockIdx.z) {
        case 0: X = DU; W = uu_iw;              bias = uu_ib;          out = g_q_uu;  break;
        case 1: X = DU; W = ta_iw;              bias = ta_ib;          out = g_q_ta;  break;
        case 2: X = DU; W = du_iw;              bias = du_ib;          out = g_q_du;  break;
        case 3: X = TA; W = ta_iw + Ec * Ec;    bias = ta_ib + Ec;     out = g_k_ta;  break;
        case 4: X = TA; W = ta_iw + 2 * Ec * Ec; bias = ta_ib + 2 * Ec; out = g_v_ta; break;
        case 5: X = DU; W = du_iw + Ec * Ec;    bias = du_ib + Ec;     out = g_k_du;  break;
        case 6: X = DU; W = du_iw + 2 * Ec * Ec; bias = du_ib + 2 * Ec; out = g_v_du; break;
        case 7: X = UU; W = uu_iw + Ec * Ec;    bias = uu_ib + Ec;     out = g_kb_uu;
                K = Ec - 2; sx = Ec - 2; M = Bc * NUc; break;
        default: X = UU; W = uu_iw + 2 * Ec * Ec; bias = uu_ib + 2 * Ec; out = g_vb_uu;
                K = Ec - 2; sx = Ec - 2; M = Bc * NUc; break;
    }
    int tx = threadIdx.x, ty = threadIdx.y;
    int n = blockIdx.x * 32 + tx;
    int m = blockIdx.y * 8 + ty;
    if (blockIdx.y * 8 >= M) return;   // whole block out of range (uniform)

    __shared__ float Xs[8][32];
    __shared__ float Ws[32][33];
    float acc = 0.f;
    for (int k0 = 0; k0 < K; k0 += 32) {
        int k = k0 + tx;
        Xs[ty][tx] = (k < K) ? X[(size_t)m * sx + k] : 0.f;
        #pragma unroll
        for (int i = ty; i < 32; i += 8) {
            Ws[i][tx] = (k < K) ? W[(size_t)(blockIdx.x * 32 + i) * Ec + k] : 0.f;
        }
        __syncthreads();
        #pragma unroll
        for (int kk = 0; kk < 32; kk++) acc += Xs[ty][kk] * Ws[tx][kk];
        __syncthreads();
    }
    out[(size_t)m * Ec + n] = acc + bias[n];
}

// ---------------- attention: one CTA per (b,l), one warp per head ----------------
// sel: 0 = UU (rank-2 corrected KV), 1 = TA, 2 = DU
template<int NK, bool IS_UU>
__global__ void __launch_bounds__(256) attn(int sel, const float* __restrict__ CI,
                                            const float* __restrict__ inw)
{
    constexpr int NPL = NK / 32;
    const float *Q, *Kb, *Vb;
    float* O;
    if (sel == 0)      { Q = g_q_uu; Kb = g_kb_uu; Vb = g_vb_uu; O = g_o_uu; }
    else if (sel == 1) { Q = g_q_ta; Kb = g_k_ta;  Vb = g_v_ta;  O = g_o_ta; }
    else               { Q = g_q_du; Kb = g_k_du;  Vb = g_v_du;  O = g_o_du; }

    int bl = blockIdx.x;
    int b = bl >> 8;
    int l = bl & 255;
    int warp = threadIdx.x >> 5;
    int lane = threadIdx.x & 31;

    __shared__ float qs[Ec];
    __shared__ float ci1[NUc];
    __shared__ float ci2[NUc];

    if (threadIdx.x < Ec) qs[threadIdx.x] = Q[(size_t)bl * Ec + threadIdx.x];
    if constexpr (IS_UU) {
        for (int n = threadIdx.x; n < NUc; n += 256) {
            ci1[n] = CI[((size_t)b * NUc + n) * (2 * Lc) + l];
            ci2[n] = CI[((size_t)b * NUc + n) * (2 * Lc) + l + Lc];
        }
    }
    __syncthreads();

    int h = warp;
    float qh[Dh];
    #pragma unroll
    for (int d = 0; d < Dh; d++) qh[d] = qs[h * Dh + d];

    float c1k = 0.f, c2k = 0.f;
    float wvc1[Dh], wvc2[Dh];
    if constexpr (IS_UU) {
        #pragma unroll
        for (int d = 0; d < Dh; d++) {
            int krow = Ec + h * Dh + d;       // Wk row e
            c1k += qh[d] * inw[(size_t)krow * Ec + 126];
            c2k += qh[d] * inw[(size_t)krow * Ec + 127];
            int vrow = 2 * Ec + h * Dh + d;   // Wv row e
            wvc1[d] = inw[(size_t)vrow * Ec + 126];
            wvc2[d] = inw[(size_t)vrow * Ec + 127];
        }
    }

    float sv[NPL];
    float mx = -1e30f;
    #pragma unroll
    for (int i = 0; i < NPL; i++) {
        int n = lane + i * 32;
        const float* kr = Kb + ((size_t)(b * NK + n)) * Ec + h * Dh;
        float s = 0.f;
        #pragma unroll
        for (int d = 0; d < Dh; d++) s += qh[d] * kr[d];
        if constexpr (IS_UU) s += ci1[n] * c1k + ci2[n] * c2k;
        s *= 0.25f;   // 1/sqrt(16)
        sv[i] = s;
        mx = fmaxf(mx, s);
    }
    #pragma unroll
    for (int o = 16; o >= 1; o >>= 1) mx = fmaxf(mx, __shfl_xor_sync(0xffffffffu, mx, o));

    float sum = 0.f;
    #pragma unroll
    for (int i = 0; i < NPL; i++) { sv[i] = __expf(sv[i] - mx); sum += sv[i]; }
    #pragma unroll
    for (int o = 16; o >= 1; o >>= 1) sum += __shfl_xor_sync(0xffffffffu, sum, o);

    float acc[Dh];
    #pragma unroll
    for (int d = 0; d < Dh; d++) acc[d] = 0.f;
    float a1 = 0.f, a2 = 0.f;
    #pragma unroll
    for (int i = 0; i < NPL; i++) {
        int n = lane + i * 32;
        const float* vr = Vb + ((size_t)(b * NK + n)) * Ec + h * Dh;
        float p = sv[i];
        #pragma unroll
        for (int d = 0; d < Dh; d++) acc[d] += p * vr[d];
        if constexpr (IS_UU) { a1 += p * ci1[n]; a2 += p * ci2[n]; }
    }
    #pragma unroll
    for (int d = 0; d < Dh; d++) {
        #pragma unroll
        for (int o = 16; o >= 1; o >>= 1) acc[d] += __shfl_xor_sync(0xffffffffu, acc[d], o);
    }
    if constexpr (IS_UU) {
        #pragma unroll
        for (int o = 16; o >= 1; o >>= 1) {
            a1 += __shfl_xor_sync(0xffffffffu, a1, o);
            a2 += __shfl_xor_sync(0xffffffffu, a2, o);
        }
    }

    if (lane == 0) {
        float inv = 1.f / sum;
        #pragma unroll
        for (int d = 0; d < Dh; d++) {
            float v = acc[d];
            if constexpr (IS_UU) v += a1 * wvc1[d] + a2 * wvc2[d];
            O[(size_t)bl * Ec + h * Dh + d] = v * inv;
        }
    }
}

// ---------------- final combined projection: y = o_uu@W1^T + o_ta@W2^T + o_du@W3^T + b ----------------
__global__ void final_y()
{
    int bl = blockIdx.x;
    int t = threadIdx.x;
    __shared__ float ou[Ec], ot[Ec], od[Ec];
    ou[t] = g_o_uu[(size_t)bl * Ec + t];
    ot[t] = g_o_ta[(size_t)bl * Ec + t];
    od[t] = g_o_du[(size_t)bl * Ec + t];
    __syncthreads();
    float acc = g_bcomb[t];
    #pragma unroll 4
    for (int j = 0; j < Ec; j++) {
        acc += ou[j] * g_W1T[j * Ec + t] + ot[j] * g_W2T[j * Ec + t] + od[j] * g_W3T[j * Ec + t];
    }
    g_y[(size_t)bl * Ec + t] = acc;
}

// ---------------- batchnorm stats (training mode, biased var over B*L) ----------------
__global__ void bn_stats()
{
    int e = blockIdx.x;
    int t = threadIdx.x;
    float s = 0.f, s2 = 0.f;
    for (int r = t; r < Bc * Lc; r += 256) {
        float v = g_y[(size_t)r * Ec + e];
        s += v;
        s2 += v * v;
    }
    __shared__ float ss[256], ss2[256];
    ss[t] = s; ss2[t] = s2;
    __syncthreads();
    for (int o = 128; o >= 1; o >>= 1) {
        if (t < o) { ss[t] += ss[t + o]; ss2[t] += ss2[t + o]; }
        __syncthreads();
    }
    if (t == 0) {
        float mean = ss[0] / (Bc * Lc);
        float var = ss2[0] / (Bc * Lc) - mean * mean;
        g_mean[e] = mean;
        g_rstd[e] = rsqrtf(var + 1e-5f);
    }
}

// ---------------- normalize + relu ----------------
__global__ void bn_apply(const float* __restrict__ gamma, const float* __restrict__ beta,
                         float* __restrict__ out)
{
    int i = blockIdx.x * 256 + threadIdx.x;
    int e = i & (Ec - 1);
    float v = (g_y[i] - g_mean[e]) * g_rstd[e] * gamma[e] + beta[e];
    out[i] = fmaxf(v, 0.f);
}

extern "C" void kernel_launch(void* const* d_in, const int* in_sizes, int n_in,
                              void* d_out, int out_size)
{
    const float* UUMat   = (const float*)d_in[0];
    const float* DUMat   = (const float*)d_in[1];
    const float* TAMat   = (const float*)d_in[2];
    const float* CIMat   = (const float*)d_in[3];
    const float* uu_in_w = (const float*)d_in[4];
    const float* uu_in_b = (const float*)d_in[5];
    const float* uu_out_w= (const float*)d_in[6];
    const float* uu_out_b= (const float*)d_in[7];
    const float* ta_in_w = (const float*)d_in[8];
    const float* ta_in_b = (const float*)d_in[9];
    const float* ta_out_w= (const float*)d_in[10];
    const float* ta_out_b= (const float*)d_in[11];
    const float* du_in_w = (const float*)d_in[12];
    const float* du_in_b = (const float*)d_in[13];
    const float* du_out_w= (const float*)d_in[14];
    const float* du_out_b= (const float*)d_in[15];
    const float* dim_w   = (const float*)d_in[16];
    const float* dim_b   = (const float*)d_in[17];
    const float* bn_gamma= (const float*)d_in[18];
    const float* bn_beta = (const float*)d_in[19];
    float* out = (float*)d_out;

    combine_w<<<(3 * Ec * Ec + Ec + 255) / 256, 256>>>(
        dim_w, dim_b, uu_out_w, uu_out_b, ta_out_w, ta_out_b, du_out_w, du_out_b);

    proj_all<<<dim3(4, 256, 9), dim3(32, 8)>>>(
        UUMat, DUMat, TAMat, uu_in_w, uu_in_b, ta_in_w, ta_in_b, du_in_w, du_in_b);

    attn<NUc, true><<<Bc * Lc, 256>>>(0, CIMat, uu_in_w);
    attn<NTc, false><<<Bc * Lc, 256>>>(1, nullptr, nullptr);
    attn<Lc, false><<<Bc * Lc, 256>>>(2, nullptr, nullptr);

    final_y<<<Bc * Lc, Ec>>>();
    bn_stats<<<Ec, 256>>>();
    bn_apply<<<(Bc * Lc * Ec) / 256, 256>>>(bn_gamma, bn_beta, out);
}

// round 3
// speedup vs baseline: 6.5648x; 6.5648x over previous
#include <cuda_runtime.h>
#include <math.h>

#define Bc 4
#define Lc 256
#define Ec 128
#define Hc 8
#define Dh 16
#define NUc 512
#define NTc 256

// ---------------- scratch (device globals; no allocation) ----------------
__device__ float g_q_uu[Bc*Lc*Ec];
__device__ float g_q_ta[Bc*Lc*Ec];
__device__ float g_q_du[Bc*Lc*Ec];
__device__ float g_k_ta[Bc*NTc*Ec];   // head-blocked [b][h][n][16]
__device__ float g_v_ta[Bc*NTc*Ec];
__device__ float g_k_du[Bc*Lc*Ec];
__device__ float g_v_du[Bc*Lc*Ec];
__device__ float g_kb_uu[Bc*NUc*Ec];
__device__ float g_vb_uu[Bc*NUc*Ec];
__device__ float g_ciT[Bc*2*Lc*NUc];  // [b][j][n]
__device__ float g_o_uu[Bc*Lc*Ec];
__device__ float g_o_ta[Bc*Lc*Ec];
__device__ float g_o_du[Bc*Lc*Ec];
__device__ float g_W1T[Ec*Ec];
__device__ float g_W2T[Ec*Ec];
__device__ float g_W3T[Ec*Ec];
__device__ float g_bcomb[Ec];
__device__ float g_y[Bc*Lc*Ec];
__device__ float g_mean[Ec];
__device__ float g_rstd[Ec];

// ---------------- combined output-projection weights ----------------
__global__ void combine_w(const float* __restrict__ dim_w, const float* __restrict__ dim_b,
                          const float* __restrict__ uu_ow, const float* __restrict__ uu_ob,
                          const float* __restrict__ ta_ow, const float* __restrict__ ta_ob,
                          const float* __restrict__ du_ow, const float* __restrict__ du_ob)
{
    int tid = blockIdx.x * 256 + threadIdx.x;
    if (tid < 3 * Ec * Ec) {
        int m = tid / (Ec * Ec);
        int rem = tid % (Ec * Ec);
        int j = rem / Ec;
        int e = rem % Ec;
        const float* ow = (m == 0) ? uu_ow : (m == 1) ? ta_ow : du_ow;
        const float* dw = dim_w + (size_t)e * (3 * Ec) + m * Ec;
        float acc = 0.f;
        #pragma unroll 4
        for (int k = 0; k < Ec; k++) acc += dw[k] * ow[k * Ec + j];
        float* dst = (m == 0) ? g_W1T : (m == 1) ? g_W2T : g_W3T;
        dst[j * Ec + e] = acc;
    } else if (tid < 3 * Ec * Ec + Ec) {
        int e = tid - 3 * Ec * Ec;
        float acc = dim_b[e];
        const float* dw = dim_w + (size_t)e * (3 * Ec);
        for (int k = 0; k < Ec; k++) {
            acc += dw[k] * uu_ob[k] + dw[Ec + k] * ta_ob[k] + dw[2 * Ec + k] * du_ob[k];
        }
        g_bcomb[e] = acc;
    }
}

// ---------------- transpose CI: [B][NU][2L] -> [B][2L][NU] ----------------
__global__ void ci_transpose(const float* __restrict__ CI)
{
    __shared__ float t[32][33];
    int n0 = blockIdx.x * 32, j0 = blockIdx.y * 32, b = blockIdx.z;
    int tx = threadIdx.x, ty = threadIdx.y;
    #pragma unroll
    for (int r = 0; r < 4; r++) {
        int n = n0 + ty + 8 * r;
        t[ty + 8 * r][tx] = CI[((size_t)b * NUc + n) * (2 * Lc) + j0 + tx];
    }
    __syncthreads();
    #pragma unroll
    for (int r = 0; r < 4; r++) {
        int j = j0 + ty + 8 * r;
        g_ciT[((size_t)b * 2 * Lc + j) * NUc + n0 + tx] = t[tx][ty + 8 * r];
    }
}

// ---------------- input projections, 32x32 tiles, 4 rows/thread ----------------
__global__ void proj_all(const float* __restrict__ UU, const float* __restrict__ DU,
                         const float* __restrict__ TA,
                         const float* __restrict__ uu_iw, const float* __restrict__ uu_ib,
                         const float* __restrict__ ta_iw, const float* __restrict__ ta_ib,
                         const float* __restrict__ du_iw, const float* __restrict__ du_ib)
{
    const float *X, *W, *bias;
    float* out;
    int K = Ec, sx = Ec, M = Bc * Lc, R = 0;
    switch (blockIdx.z) {
        case 0: X = DU; W = uu_iw;               bias = uu_ib;           out = g_q_uu;  break;
        case 1: X = DU; W = ta_iw;               bias = ta_ib;           out = g_q_ta;  break;
        case 2: X = DU; W = du_iw;               bias = du_ib;           out = g_q_du;  break;
        case 3: X = TA; W = ta_iw + Ec * Ec;     bias = ta_ib + Ec;      out = g_k_ta;  R = NTc; break;
        case 4: X = TA; W = ta_iw + 2 * Ec * Ec; bias = ta_ib + 2 * Ec;  out = g_v_ta;  R = NTc; break;
        case 5: X = DU; W = du_iw + Ec * Ec;     bias = du_ib + Ec;      out = g_k_du;  R = Lc;  break;
        case 6: X = DU; W = du_iw + 2 * Ec * Ec; bias = du_ib + 2 * Ec;  out = g_v_du;  R = Lc;  break;
        case 7: X = UU; W = uu_iw + Ec * Ec;     bias = uu_ib + Ec;      out = g_kb_uu;
                K = Ec - 2; sx = Ec - 2; M = Bc * NUc; R = NUc; break;
        default: X = UU; W = uu_iw + 2 * Ec * Ec; bias = uu_ib + 2 * Ec; out = g_vb_uu;
                K = Ec - 2; sx = Ec - 2; M = Bc * NUc; R = NUc; break;
    }
    int m0 = blockIdx.y * 32;
    if (m0 >= M) return;
    int n0 = blockIdx.x * 32;
    int tx = threadIdx.x, ty = threadIdx.y;

    __shared__ float Xs[32][33];
    __shared__ float Ws[32][33];
    float acc[4] = {0.f, 0.f, 0.f, 0.f};
    for (int k0 = 0; k0 < K; k0 += 32) {
        int k = k0 + tx;
        #pragma unroll
        for (int r = 0; r < 4; r++) {
            int row = ty + 8 * r;
            Xs[row][tx] = (k < K) ? X[(size_t)(m0 + row) * sx + k] : 0.f;
            Ws[row][tx] = (k < K) ? W[(size_t)(n0 + row) * Ec + k] : 0.f;
        }
        __syncthreads();
        #pragma unroll
        for (int kk = 0; kk < 32; kk++) {
            float wv = Ws[tx][kk];
            #pragma unroll
            for (int r = 0; r < 4; r++) acc[r] += Xs[ty + 8 * r][kk] * wv;
        }
        __syncthreads();
    }
    int n = n0 + tx;
    float bv = bias[n];
    #pragma unroll
    for (int r = 0; r < 4; r++) {
        int m = m0 + ty + 8 * r;
        float v = acc[r] + bv;
        if (R == 0) {
            out[(size_t)m * Ec + n] = v;
        } else {
            int bb = m / R, row = m % R;
            out[(((size_t)bb * Hc + (n >> 4)) * R + row) * Dh + (n & 15)] = v;
        }
    }
}

// ---------------- warp reductions ----------------
__device__ __forceinline__ float wred_sum(float v) {
    #pragma unroll
    for (int o = 16; o >= 1; o >>= 1) v += __shfl_xor_sync(0xffffffffu, v, o);
    return v;
}
__device__ __forceinline__ float wred_max(float v) {
    #pragma unroll
    for (int o = 16; o >= 1; o >>= 1) v = fmaxf(v, __shfl_xor_sync(0xffffffffu, v, o));
    return v;
}

// ---------------- attention: SMEM-staged K/V, 32 queries per CTA ----------------
// grid (L/32, H, B), 128 threads (4 warps, 8 queries each)
template<int NK, bool IS_UU>
__global__ void __launch_bounds__(128) attn2(int sel, const float* __restrict__ inw)
{
    constexpr int NPL = NK / 32;
    extern __shared__ float4 sm4[];
    float4* Ks4 = sm4;            // [NK][5] float4, row pad 20 floats
    float4* Vs4 = sm4 + NK * 5;

    const float *Q, *Kb, *Vb;
    float* O;
    if (sel == 0)      { Q = g_q_uu; Kb = g_kb_uu; Vb = g_vb_uu; O = g_o_uu; }
    else if (sel == 1) { Q = g_q_ta; Kb = g_k_ta;  Vb = g_v_ta;  O = g_o_ta; }
    else               { Q = g_q_du; Kb = g_k_du;  Vb = g_v_du;  O = g_o_du; }

    int b = blockIdx.z, h = blockIdx.y, lt = blockIdx.x;
    int tid = threadIdx.x, warp = tid >> 5, lane = tid & 31;

    {
        const float4* ks = (const float4*)(Kb + ((size_t)(b * Hc + h) * NK) * Dh);
        const float4* vs = (const float4*)(Vb + ((size_t)(b * Hc + h) * NK) * Dh);
        for (int i = tid; i < NK * 4; i += 128) {
            int row = i >> 2, j = i & 3;
            Ks4[row * 5 + j] = ks[i];
            Vs4[row * 5 + j] = vs[i];
        }
    }
    __syncthreads();

    for (int ql = warp; ql < 32; ql += 4) {
        int l = lt * 32 + ql;
        int bl = b * Lc + l;
        const float* qp = Q + (size_t)bl * Ec + h * Dh;
        float q[16];
        #pragma unroll
        for (int d = 0; d < 16; d++) q[d] = __ldg(qp + d);

        float c1k = 0.f, c2k = 0.f;
        const float *cp1 = nullptr, *cp2 = nullptr;
        if constexpr (IS_UU) {
            #pragma unroll
            for (int d = 0; d < 16; d++) {
                size_t kr = (size_t)(Ec + h * Dh + d) * Ec;
                c1k += q[d] * __ldg(inw + kr + 126);
                c2k += q[d] * __ldg(inw + kr + 127);
            }
            cp1 = g_ciT + ((size_t)b * 2 * Lc + l) * NUc;
            cp2 = cp1 + (size_t)Lc * NUc;
        }

        float sv[NPL];
        float mx = -1e30f;
        #pragma unroll
        for (int i = 0; i < NPL; i++) {
            int n = i * 32 + lane;
            const float4* kr = Ks4 + n * 5;
            float4 k0 = kr[0], k1 = kr[1], k2 = kr[2], k3 = kr[3];
            float s = q[0]*k0.x + q[1]*k0.y + q[2]*k0.z + q[3]*k0.w
                    + q[4]*k1.x + q[5]*k1.y + q[6]*k1.z + q[7]*k1.w
                    + q[8]*k2.x + q[9]*k2.y + q[10]*k2.z + q[11]*k2.w
                    + q[12]*k3.x + q[13]*k3.y + q[14]*k3.z + q[15]*k3.w;
            if constexpr (IS_UU) s += cp1[n] * c1k + cp2[n] * c2k;
            s *= 0.25f;
            sv[i] = s;
            mx = fmaxf(mx, s);
        }
        mx = wred_max(mx);
        float sum = 0.f;
        #pragma unroll
        for (int i = 0; i < NPL; i++) { sv[i] = __expf(sv[i] - mx); sum += sv[i]; }
        sum = wred_sum(sum);

        float a[16];
        #pragma unroll
        for (int d = 0; d < 16; d++) a[d] = 0.f;
        float A1 = 0.f, A2 = 0.f;
        #pragma unroll
        for (int i = 0; i < NPL; i++) {
            int n = i * 32 + lane;
            const float4* vr = Vs4 + n * 5;
            float4 v0 = vr[0], v1 = vr[1], v2 = vr[2], v3 = vr[3];
            float p = sv[i];
            a[0] += p*v0.x;  a[1] += p*v0.y;  a[2] += p*v0.z;  a[3] += p*v0.w;
            a[4] += p*v1.x;  a[5] += p*v1.y;  a[6] += p*v1.z;  a[7] += p*v1.w;
            a[8] += p*v2.x;  a[9] += p*v2.y;  a[10] += p*v2.z; a[11] += p*v2.w;
            a[12] += p*v3.x; a[13] += p*v3.y; a[14] += p*v3.z; a[15] += p*v3.w;
            if constexpr (IS_UU) { A1 += p * cp1[n]; A2 += p * cp2[n]; }
        }
        #pragma unroll
        for (int d = 0; d < 16; d++) a[d] = wred_sum(a[d]);
        if constexpr (IS_UU) { A1 = wred_sum(A1); A2 = wred_sum(A2); }

        if (lane == 0) {
            float inv = 1.f / sum;
            float o16[16];
            #pragma unroll
            for (int d = 0; d < 16; d++) {
                float v = a[d];
                if constexpr (IS_UU) {
                    size_t vr = (size_t)(2 * Ec + h * Dh + d) * Ec;
                    v += A1 * __ldg(inw + vr + 126) + A2 * __ldg(inw + vr + 127);
                }
                o16[d] = v * inv;
            }
            float4* op = (float4*)(O + (size_t)bl * Ec + h * Dh);
            op[0] = make_float4(o16[0], o16[1], o16[2], o16[3]);
            op[1] = make_float4(o16[4], o16[5], o16[6], o16[7]);
            op[2] = make_float4(o16[8], o16[9], o16[10], o16[11]);
            op[3] = make_float4(o16[12], o16[13], o16[14], o16[15]);
        }
    }
}

// ---------------- final combined projection ----------------
__global__ void final_y()
{
    int bl = blockIdx.x;
    int t = threadIdx.x;
    __shared__ float ou[Ec], ot[Ec], od[Ec];
    ou[t] = g_o_uu[(size_t)bl * Ec + t];
    ot[t] = g_o_ta[(size_t)bl * Ec + t];
    od[t] = g_o_du[(size_t)bl * Ec + t];
    __syncthreads();
    float acc = g_bcomb[t];
    #pragma unroll 4
    for (int j = 0; j < Ec; j++) {
        acc += ou[j] * g_W1T[j * Ec + t] + ot[j] * g_W2T[j * Ec + t] + od[j] * g_W3T[j * Ec + t];
    }
    g_y[(size_t)bl * Ec + t] = acc;
}

// ---------------- batchnorm stats ----------------
__global__ void bn_stats()
{
    int e = blockIdx.x;
    int t = threadIdx.x;
    float s = 0.f, s2 = 0.f;
    for (int r = t; r < Bc * Lc; r += 256) {
        float v = g_y[(size_t)r * Ec + e];
        s += v;
        s2 += v * v;
    }
    __shared__ float ss[256], ss2[256];
    ss[t] = s; ss2[t] = s2;
    __syncthreads();
    for (int o = 128; o >= 1; o >>= 1) {
        if (t < o) { ss[t] += ss[t + o]; ss2[t] += ss2[t + o]; }
        __syncthreads();
    }
    if (t == 0) {
        float mean = ss[0] / (Bc * Lc);
        float var = ss2[0] / (Bc * Lc) - mean * mean;
        g_mean[e] = mean;
        g_rstd[e] = rsqrtf(var + 1e-5f);
    }
}

__global__ void bn_apply(const float* __restrict__ gamma, const float* __restrict__ beta,
                         float* __restrict__ out)
{
    int i = blockIdx.x * 256 + threadIdx.x;
    int e = i & (Ec - 1);
    float v = (g_y[i] - g_mean[e]) * g_rstd[e] * gamma[e] + beta[e];
    out[i] = fmaxf(v, 0.f);
}

extern "C" void kernel_launch(void* const* d_in, const int* in_sizes, int n_in,
                              void* d_out, int out_size)
{
    const float* UUMat   = (const float*)d_in[0];
    const float* DUMat   = (const float*)d_in[1];
    const float* TAMat   = (const float*)d_in[2];
    const float* CIMat   = (const float*)d_in[3];
    const float* uu_in_w = (const float*)d_in[4];
    const float* uu_in_b = (const float*)d_in[5];
    const float* uu_out_w= (const float*)d_in[6];
    const float* uu_out_b= (const float*)d_in[7];
    const float* ta_in_w = (const float*)d_in[8];
    const float* ta_in_b = (const float*)d_in[9];
    const float* ta_out_w= (const float*)d_in[10];
    const float* ta_out_b= (const float*)d_in[11];
    const float* du_in_w = (const float*)d_in[12];
    const float* du_in_b = (const float*)d_in[13];
    const float* du_out_w= (const float*)d_in[14];
    const float* du_out_b= (const float*)d_in[15];
    const float* dim_w   = (const float*)d_in[16];
    const float* dim_b   = (const float*)d_in[17];
    const float* bn_gamma= (const float*)d_in[18];
    const float* bn_beta = (const float*)d_in[19];
    float* out = (float*)d_out;

    // UU attn needs 80 KB dynamic smem
    cudaFuncSetAttribute(attn2<NUc, true>, cudaFuncAttributeMaxDynamicSharedMemorySize,
                         2 * NUc * 5 * (int)sizeof(float4));

    combine_w<<<(3 * Ec * Ec + Ec + 255) / 256, 256>>>(
        dim_w, dim_b, uu_out_w, uu_out_b, ta_out_w, ta_out_b, du_out_w, du_out_b);

    ci_transpose<<<dim3(NUc / 32, 2 * Lc / 32, Bc), dim3(32, 8)>>>(CIMat);

    proj_all<<<dim3(4, 64, 9), dim3(32, 8)>>>(
        UUMat, DUMat, TAMat, uu_in_w, uu_in_b, ta_in_w, ta_in_b, du_in_w, du_in_b);

    attn2<NUc, true><<<dim3(Lc / 32, Hc, Bc), 128, 2 * NUc * 5 * sizeof(float4)>>>(0, uu_in_w);
    attn2<NTc, false><<<dim3(Lc / 32, Hc, Bc), 128, 2 * NTc * 5 * sizeof(float4)>>>(1, nullptr);
    attn2<Lc,  false><<<dim3(Lc / 32, Hc, Bc), 128, 2 * Lc * 5 * sizeof(float4)>>>(2, nullptr);

    final_y<<<Bc * Lc, Ec>>>();
    bn_stats<<<Ec, 256>>>();
    bn_apply<<<(Bc * Lc * Ec) / 256, 256>>>(bn_gamma, bn_beta, out);
}

// round 4
// speedup vs baseline: 8.1525x; 1.2419x over previous
#include <cuda_runtime.h>
#include <math.h>

#define Bc 4
#define Lc 256
#define Ec 128
#define Hc 8
#define Dh 16
#define NUc 512
#define NTc 256

// ---------------- scratch (device globals; no allocation) ----------------
__device__ float g_q_uu[Bc*Lc*Ec];
__device__ float g_q_ta[Bc*Lc*Ec];
__device__ float g_q_du[Bc*Lc*Ec];
__device__ float g_k_ta[Bc*NTc*Ec];   // head-blocked [b][h][n][16]
__device__ float g_v_ta[Bc*NTc*Ec];
__device__ float g_k_du[Bc*Lc*Ec];
__device__ float g_v_du[Bc*Lc*Ec];
__device__ float g_kb_uu[Bc*NUc*Ec];
__device__ float g_vb_uu[Bc*NUc*Ec];
__device__ float g_ciT[Bc*2*Lc*NUc];  // [b][j][n]
__device__ float g_o_uu[Bc*Lc*Ec];
__device__ float g_o_ta[Bc*Lc*Ec];
__device__ float g_o_du[Bc*Lc*Ec];
__device__ float g_W1T[Ec*Ec];
__device__ float g_W2T[Ec*Ec];
__device__ float g_W3T[Ec*Ec];
__device__ float g_bcomb[Ec];
__device__ float g_y[Bc*Lc*Ec];
__device__ float g_mean[Ec];
__device__ float g_rstd[Ec];

// ---------------- combined output projection weights, tiled ----------------
// W_m[e,j] = sum_k dim_w[e, m*128+k] * ow_m[k, j];  stored as WmT[j*128+e]
__global__ void combine_w2(const float* __restrict__ dim_w,
                           const float* __restrict__ uu_ow,
                           const float* __restrict__ ta_ow,
                           const float* __restrict__ du_ow)
{
    int m = blockIdx.z;
    const float* ow = (m == 0) ? uu_ow : (m == 1) ? ta_ow : du_ow;
    float* dst = (m == 0) ? g_W1T : (m == 1) ? g_W2T : g_W3T;
    int e0 = blockIdx.x * 32, j0 = blockIdx.y * 32;
    int tx = threadIdx.x, ty = threadIdx.y;

    __shared__ float dws[32][33];   // [e_local][k_local]
    __shared__ float ows[32][33];   // [k_local][j_local]
    float acc[4] = {0.f, 0.f, 0.f, 0.f};
    for (int k0 = 0; k0 < Ec; k0 += 32) {
        #pragma unroll
        for (int r = 0; r < 4; r++) {
            int row = ty + 8 * r;
            dws[row][tx] = dim_w[(size_t)(e0 + row) * (3 * Ec) + m * Ec + k0 + tx];
            ows[row][tx] = ow[(size_t)(k0 + row) * Ec + j0 + tx];
        }
        __syncthreads();
        #pragma unroll
        for (int kk = 0; kk < 32; kk++) {
            float d = dws[tx][kk];
            #pragma unroll
            for (int r = 0; r < 4; r++) acc[r] += d * ows[kk][ty + 8 * r];
        }
        __syncthreads();
    }
    #pragma unroll
    for (int r = 0; r < 4; r++)
        dst[(size_t)(j0 + ty + 8 * r) * Ec + e0 + tx] = acc[r];
}

// bias: bcomb[e] = dim_b[e] + sum_k dim_w[e,k] * cat(ob)[k]
__global__ void combine_b(const float* __restrict__ dim_w, const float* __restrict__ dim_b,
                          const float* __restrict__ uu_ob, const float* __restrict__ ta_ob,
                          const float* __restrict__ du_ob)
{
    int warp = threadIdx.x >> 5, lane = threadIdx.x & 31;
    for (int e = warp; e < Ec; e += 4) {
        float s = 0.f;
        #pragma unroll
        for (int i = 0; i < 12; i++) {
            int k = lane + 32 * i;
            const float* ob = (i < 4) ? uu_ob : (i < 8) ? ta_ob : du_ob;
            int kl = k - (i < 4 ? 0 : (i < 8 ? Ec : 2 * Ec));
            s += dim_w[(size_t)e * (3 * Ec) + k] * ob[kl];
        }
        #pragma unroll
        for (int o = 16; o >= 1; o >>= 1) s += __shfl_xor_sync(0xffffffffu, s, o);
        if (lane == 0) g_bcomb[e] = dim_b[e] + s;
    }
}

// ---------------- transpose CI: [B][NU][2L] -> [B][2L][NU] ----------------
__global__ void ci_transpose(const float* __restrict__ CI)
{
    __shared__ float t[32][33];
    int n0 = blockIdx.x * 32, j0 = blockIdx.y * 32, b = blockIdx.z;
    int tx = threadIdx.x, ty = threadIdx.y;
    #pragma unroll
    for (int r = 0; r < 4; r++) {
        int n = n0 + ty + 8 * r;
        t[ty + 8 * r][tx] = CI[((size_t)b * NUc + n) * (2 * Lc) + j0 + tx];
    }
    __syncthreads();
    #pragma unroll
    for (int r = 0; r < 4; r++) {
        int j = j0 + ty + 8 * r;
        g_ciT[((size_t)b * 2 * Lc + j) * NUc + n0 + tx] = t[tx][ty + 8 * r];
    }
}

// ---------------- input projections, 32x32 tiles, 4 rows/thread ----------------
__global__ void proj_all(const float* __restrict__ UU, const float* __restrict__ DU,
                         const float* __restrict__ TA,
                         const float* __restrict__ uu_iw, const float* __restrict__ uu_ib,
                         const float* __restrict__ ta_iw, const float* __restrict__ ta_ib,
                         const float* __restrict__ du_iw, const float* __restrict__ du_ib)
{
    const float *X, *W, *bias;
    float* out;
    int K = Ec, sx = Ec, M = Bc * Lc, R = 0;
    switch (blockIdx.z) {
        case 0: X = DU; W = uu_iw;               bias = uu_ib;           out = g_q_uu;  break;
        case 1: X = DU; W = ta_iw;               bias = ta_ib;           out = g_q_ta;  break;
        case 2: X = DU; W = du_iw;               bias = du_ib;           out = g_q_du;  break;
        case 3: X = TA; W = ta_iw + Ec * Ec;     bias = ta_ib + Ec;      out = g_k_ta;  R = NTc; break;
        case 4: X = TA; W = ta_iw + 2 * Ec * Ec; bias = ta_ib + 2 * Ec;  out = g_v_ta;  R = NTc; break;
        case 5: X = DU; W = du_iw + Ec * Ec;     bias = du_ib + Ec;      out = g_k_du;  R = Lc;  break;
        case 6: X = DU; W = du_iw + 2 * Ec * Ec; bias = du_ib + 2 * Ec;  out = g_v_du;  R = Lc;  break;
        case 7: X = UU; W = uu_iw + Ec * Ec;     bias = uu_ib + Ec;      out = g_kb_uu;
                K = Ec - 2; sx = Ec - 2; M = Bc * NUc; R = NUc; break;
        default: X = UU; W = uu_iw + 2 * Ec * Ec; bias = uu_ib + 2 * Ec; out = g_vb_uu;
                K = Ec - 2; sx = Ec - 2; M = Bc * NUc; R = NUc; break;
    }
    int m0 = blockIdx.y * 32;
    if (m0 >= M) return;
    int n0 = blockIdx.x * 32;
    int tx = threadIdx.x, ty = threadIdx.y;

    __shared__ float Xs[32][33];
    __shared__ float Ws[32][33];
    float acc[4] = {0.f, 0.f, 0.f, 0.f};
    for (int k0 = 0; k0 < K; k0 += 32) {
        int k = k0 + tx;
        #pragma unroll
        for (int r = 0; r < 4; r++) {
            int row = ty + 8 * r;
            Xs[row][tx] = (k < K) ? X[(size_t)(m0 + row) * sx + k] : 0.f;
            Ws[row][tx] = (k < K) ? W[(size_t)(n0 + row) * Ec + k] : 0.f;
        }
        __syncthreads();
        #pragma unroll
        for (int kk = 0; kk < 32; kk++) {
            float wv = Ws[tx][kk];
            #pragma unroll
            for (int r = 0; r < 4; r++) acc[r] += Xs[ty + 8 * r][kk] * wv;
        }
        __syncthreads();
    }
    int n = n0 + tx;
    float bv = bias[n];
    #pragma unroll
    for (int r = 0; r < 4; r++) {
        int m = m0 + ty + 8 * r;
        float v = acc[r] + bv;
        if (R == 0) {
            out[(size_t)m * Ec + n] = v;
        } else {
            int bb = m / R, row = m % R;
            out[(((size_t)bb * Hc + (n >> 4)) * R + row) * Dh + (n & 15)] = v;
        }
    }
}

__device__ __forceinline__ float wred_sum(float v) {
    #pragma unroll
    for (int o = 16; o >= 1; o >>= 1) v += __shfl_xor_sync(0xffffffffu, v, o);
    return v;
}
__device__ __forceinline__ float wred_max(float v) {
    #pragma unroll
    for (int o = 16; o >= 1; o >>= 1) v = fmaxf(v, __shfl_xor_sync(0xffffffffu, v, o));
    return v;
}

// ---------------- attention v3: reused SMEM buffer, 4 queries/warp ----------------
// 128 threads (4 warps), 16 queries per CTA.
// grid (L/16, H, B) for UU; grid (L/16, H, 2B) for TA+DU merged (z<B: TA, else DU).
template<int NK, bool IS_UU>
__global__ void __launch_bounds__(128, 3) attn3(const float* __restrict__ inw)
{
    constexpr int NPL = NK / 32;
    extern __shared__ float4 sm4[];   // [NK][5] float4 rows (pad 20 floats)

    const float *Q, *Kb, *Vb;
    float* O;
    int b;
    if constexpr (IS_UU) {
        b = blockIdx.z;
        Q = g_q_uu; Kb = g_kb_uu; Vb = g_vb_uu; O = g_o_uu;
    } else {
        if (blockIdx.z < Bc) { b = blockIdx.z;      Q = g_q_ta; Kb = g_k_ta; Vb = g_v_ta; O = g_o_ta; }
        else                 { b = blockIdx.z - Bc; Q = g_q_du; Kb = g_k_du; Vb = g_v_du; O = g_o_du; }
    }
    int h = blockIdx.y, lt = blockIdx.x;
    int tid = threadIdx.x, warp = tid >> 5, lane = tid & 31;

    const float4* ksrc = (const float4*)(Kb + ((size_t)(b * Hc + h) * NK) * Dh);
    const float4* vsrc = (const float4*)(Vb + ((size_t)(b * Hc + h) * NK) * Dh);

    // phase 0: K into smem
    for (int i = tid; i < NK * 4; i += 128) sm4[(i >> 2) * 5 + (i & 3)] = ksrc[i];
    __syncthreads();

    int l0 = lt * 16 + warp * 4;
    int bl0 = b * Lc + l0;

    float q[4][16];
    #pragma unroll
    for (int qi = 0; qi < 4; qi++) {
        const float4* qp = (const float4*)(Q + (size_t)(bl0 + qi) * Ec + h * Dh);
        #pragma unroll
        for (int j = 0; j < 4; j++) {
            float4 t = qp[j];
            q[qi][j*4+0] = t.x; q[qi][j*4+1] = t.y; q[qi][j*4+2] = t.z; q[qi][j*4+3] = t.w;
        }
    }

    float c1k[4], c2k[4];
    const float *cp1[4], *cp2[4];
    if constexpr (IS_UU) {
        #pragma unroll
        for (int qi = 0; qi < 4; qi++) { c1k[qi] = 0.f; c2k[qi] = 0.f; }
        #pragma unroll
        for (int d = 0; d < 16; d++) {
            size_t kr = (size_t)(Ec + h * Dh + d) * Ec;
            float w1 = __ldg(inw + kr + 126), w2 = __ldg(inw + kr + 127);
            #pragma unroll
            for (int qi = 0; qi < 4; qi++) { c1k[qi] += q[qi][d] * w1; c2k[qi] += q[qi][d] * w2; }
        }
        #pragma unroll
        for (int qi = 0; qi < 4; qi++) {
            cp1[qi] = g_ciT + ((size_t)b * 2 * Lc + (l0 + qi)) * NUc;
            cp2[qi] = cp1[qi] + (size_t)Lc * NUc;
        }
    }

    // phase 1: scores
    float sv[4][NPL];
    float mx[4] = {-1e30f, -1e30f, -1e30f, -1e30f};
    #pragma unroll
    for (int i = 0; i < NPL; i++) {
        int n = i * 32 + lane;
        const float4* kr = sm4 + n * 5;
        float4 k0 = kr[0], k1 = kr[1], k2 = kr[2], k3 = kr[3];
        #pragma unroll
        for (int qi = 0; qi < 4; qi++) {
            float s = q[qi][0]*k0.x + q[qi][1]*k0.y + q[qi][2]*k0.z + q[qi][3]*k0.w
                    + q[qi][4]*k1.x + q[qi][5]*k1.y + q[qi][6]*k1.z + q[qi][7]*k1.w
                    + q[qi][8]*k2.x + q[qi][9]*k2.y + q[qi][10]*k2.z + q[qi][11]*k2.w
                    + q[qi][12]*k3.x + q[qi][13]*k3.y + q[qi][14]*k3.z + q[qi][15]*k3.w;
            if constexpr (IS_UU) s += cp1[qi][n] * c1k[qi] + cp2[qi][n] * c2k[qi];
            s *= 0.25f;
            sv[qi][i] = s;
            mx[qi] = fmaxf(mx[qi], s);
        }
    }
    float invsum[4];
    #pragma unroll
    for (int qi = 0; qi < 4; qi++) {
        float m = wred_max(mx[qi]);
        float sum = 0.f;
        #pragma unroll
        for (int i = 0; i < NPL; i++) { sv[qi][i] = __expf(sv[qi][i] - m); sum += sv[qi][i]; }
        invsum[qi] = 1.f / wred_sum(sum);
    }

    // phase 0b: V into the same smem
    __syncthreads();
    for (int i = tid; i < NK * 4; i += 128) sm4[(i >> 2) * 5 + (i & 3)] = vsrc[i];
    __syncthreads();

    // phase 2: AV
    float a[4][16];
    #pragma unroll
    for (int qi = 0; qi < 4; qi++)
        #pragma unroll
        for (int d = 0; d < 16; d++) a[qi][d] = 0.f;
    float A1[4] = {0.f,0.f,0.f,0.f}, A2[4] = {0.f,0.f,0.f,0.f};
    #pragma unroll
    for (int i = 0; i < NPL; i++) {
        int n = i * 32 + lane;
        const float4* vr = sm4 + n * 5;
        float4 v0 = vr[0], v1 = vr[1], v2 = vr[2], v3 = vr[3];
        #pragma unroll
        for (int qi = 0; qi < 4; qi++) {
            float p = sv[qi][i];
            a[qi][0] += p*v0.x;  a[qi][1] += p*v0.y;  a[qi][2] += p*v0.z;  a[qi][3] += p*v0.w;
            a[qi][4] += p*v1.x;  a[qi][5] += p*v1.y;  a[qi][6] += p*v1.z;  a[qi][7] += p*v1.w;
            a[qi][8] += p*v2.x;  a[qi][9] += p*v2.y;  a[qi][10]+= p*v2.z;  a[qi][11]+= p*v2.w;
            a[qi][12]+= p*v3.x;  a[qi][13]+= p*v3.y;  a[qi][14]+= p*v3.z;  a[qi][15]+= p*v3.w;
            if constexpr (IS_UU) { A1[qi] += p * cp1[qi][n]; A2[qi] += p * cp2[qi][n]; }
        }
    }
    #pragma unroll
    for (int qi = 0; qi < 4; qi++) {
        #pragma unroll
        for (int d = 0; d < 16; d++) a[qi][d] = wred_sum(a[qi][d]);
        if constexpr (IS_UU) { A1[qi] = wred_sum(A1[qi]); A2[qi] = wred_sum(A2[qi]); }
        if (lane == 0) {
            float inv = invsum[qi];
            float o16[16];
            #pragma unroll
            for (int d = 0; d < 16; d++) {
                float v = a[qi][d];
                if constexpr (IS_UU) {
                    size_t vr = (size_t)(2 * Ec + h * Dh + d) * Ec;
                    v += A1[qi] * __ldg(inw + vr + 126) + A2[qi] * __ldg(inw + vr + 127);
                }
                o16[d] = v * inv;
            }
            float4* op = (float4*)(O + (size_t)(bl0 + qi) * Ec + h * Dh);
            op[0] = make_float4(o16[0], o16[1], o16[2], o16[3]);
            op[1] = make_float4(o16[4], o16[5], o16[6], o16[7]);
            op[2] = make_float4(o16[8], o16[9], o16[10], o16[11]);
            op[3] = make_float4(o16[12], o16[13], o16[14], o16[15]);
        }
    }
}

// ---------------- final combined projection ----------------
__global__ void final_y()
{
    int bl = blockIdx.x;
    int t = threadIdx.x;
    __shared__ float ou[Ec], ot[Ec], od[Ec];
    ou[t] = g_o_uu[(size_t)bl * Ec + t];
    ot[t] = g_o_ta[(size_t)bl * Ec + t];
    od[t] = g_o_du[(size_t)bl * Ec + t];
    __syncthreads();
    float acc = g_bcomb[t];
    #pragma unroll 4
    for (int j = 0; j < Ec; j++) {
        acc += ou[j] * g_W1T[j * Ec + t] + ot[j] * g_W2T[j * Ec + t] + od[j] * g_W3T[j * Ec + t];
    }
    g_y[(size_t)bl * Ec + t] = acc;
}

// ---------------- batchnorm stats: single CTA, coalesced ----------------
__global__ void bn_stats2()
{
    __shared__ float ss[8][Ec], ss2[8][Ec];
    int t = threadIdx.x;
    int e = t & (Ec - 1), c = t >> 7;
    float s = 0.f, s2 = 0.f;
    for (int r = c * 128; r < (c + 1) * 128; r++) {
        float v = g_y[(size_t)r * Ec + e];
        s += v; s2 += v * v;
    }
    ss[c][e] = s; ss2[c][e] = s2;
    __syncthreads();
    if (t < Ec) {
        float S = 0.f, S2 = 0.f;
        #pragma unroll
        for (int i = 0; i < 8; i++) { S += ss[i][t]; S2 += ss2[i][t]; }
        float mean = S / (Bc * Lc);
        float var = S2 / (Bc * Lc) - mean * mean;
        g_mean[t] = mean;
        g_rstd[t] = rsqrtf(var + 1e-5f);
    }
}

__global__ void bn_apply(const float* __restrict__ gamma, const float* __restrict__ beta,
                         float* __restrict__ out)
{
    int i = blockIdx.x * 256 + threadIdx.x;
    int e = i & (Ec - 1);
    float v = (g_y[i] - g_mean[e]) * g_rstd[e] * gamma[e] + beta[e];
    out[i] = fmaxf(v, 0.f);
}

extern "C" void kernel_launch(void* const* d_in, const int* in_sizes, int n_in,
                              void* d_out, int out_size)
{
    const float* UUMat   = (const float*)d_in[0];
    const float* DUMat   = (const float*)d_in[1];
    const float* TAMat   = (const float*)d_in[2];
    const float* CIMat   = (const float*)d_in[3];
    const float* uu_in_w = (const float*)d_in[4];
    const float* uu_in_b = (const float*)d_in[5];
    const float* uu_out_w= (const float*)d_in[6];
    const float* uu_out_b= (const float*)d_in[7];
    const float* ta_in_w = (const float*)d_in[8];
    const float* ta_in_b = (const float*)d_in[9];
    const float* ta_out_w= (const float*)d_in[10];
    const float* ta_out_b= (const float*)d_in[11];
    const float* du_in_w = (const float*)d_in[12];
    const float* du_in_b = (const float*)d_in[13];
    const float* du_out_w= (const float*)d_in[14];
    const float* du_out_b= (const float*)d_in[15];
    const float* dim_w   = (const float*)d_in[16];
    const float* dim_b   = (const float*)d_in[17];
    const float* bn_gamma= (const float*)d_in[18];
    const float* bn_beta = (const float*)d_in[19];
    float* out = (float*)d_out;

    combine_w2<<<dim3(4, 4, 3), dim3(32, 8)>>>(dim_w, uu_out_w, ta_out_w, du_out_w);
    combine_b<<<1, 128>>>(dim_w, dim_b, uu_out_b, ta_out_b, du_out_b);

    ci_transpose<<<dim3(NUc / 32, 2 * Lc / 32, Bc), dim3(32, 8)>>>(CIMat);

    proj_all<<<dim3(4, 64, 9), dim3(32, 8)>>>(
        UUMat, DUMat, TAMat, uu_in_w, uu_in_b, ta_in_w, ta_in_b, du_in_w, du_in_b);

    attn3<NUc, true><<<dim3(Lc / 16, Hc, Bc), 128, NUc * 5 * sizeof(float4)>>>(uu_in_w);
    attn3<NTc, false><<<dim3(Lc / 16, Hc, 2 * Bc), 128, NTc * 5 * sizeof(float4)>>>(nullptr);

    final_y<<<Bc * Lc, Ec>>>();
    bn_stats2<<<1, 1024>>>();
    bn_apply<<<(Bc * Lc * Ec) / 256, 256>>>(bn_gamma, bn_beta, out);
}